// round 2
// baseline (speedup 1.0000x reference)
#include <cuda_runtime.h>
#include <cstdint>

#define FDIM 2048
#define BATCH 64
#define LOG2E 1.4426950408889634f

// scratch: q, k, v  (each 64x2048 fp32)
__device__ float g_qkv[3][BATCH * FDIM];

// ============================================================
// Phase 1: out[b,n] = sum_k x[b,k] * W[n,k]   (three weights)
// Tile: full M=64 batch x 32 n-cols, K chunked by 32.
// grid.x = 3 * (2048/32) = 192 blocks, 256 threads.
// Uses packed fma.rn.f32x2 (2 b-rows per instruction).
// ============================================================
#define KC 32
#define NT 32
#define XPITCH 68   // [k][b] tile, pitch multiple of 4 for LDS.128
#define WPITCH 34   // [k][n] tile

__global__ __launch_bounds__(256, 2) void gemm_kernel(
    const float* __restrict__ x,
    const float* __restrict__ Wq,
    const float* __restrict__ Wk,
    const float* __restrict__ Wv)
{
    __shared__ float xs[KC][XPITCH];   // xs[k][b]
    __shared__ float ws[KC][WPITCH];   // ws[k][n]

    const int bx   = blockIdx.x;
    const int wsel = bx >> 6;                 // which weight
    const int n0   = (bx & 63) * NT;
    const float* __restrict__ W = (wsel == 0) ? Wq : ((wsel == 1) ? Wk : Wv);
    float* __restrict__ out = g_qkv[wsel];

    const int tid = threadIdx.x;
    const int tx  = tid & 31;     // n within tile
    const int ty  = tid >> 5;     // b octet (8 b-rows per thread)

    // loader mapping
    const int xb = tid >> 2;            // 0..63  (b row)
    const int xk = (tid & 3) * 8;       // 0,8,16,24 (k offset, 8 floats)
    const int wn = tid >> 3;            // 0..31  (n row)
    const int wk = (tid & 7) * 4;       // 0..28  (k offset, 4 floats)

    unsigned long long acc[4];
#pragma unroll
    for (int p = 0; p < 4; p++) acc[p] = 0ull;

    float4 xr0, xr1, wr;
    {
        const float* xp = x + xb * FDIM + xk;
        xr0 = *(const float4*)(xp);
        xr1 = *(const float4*)(xp + 4);
        wr  = *(const float4*)(W + (n0 + wn) * FDIM + wk);
    }

    const int NCHUNK = FDIM / KC;   // 64
    for (int c = 0; c < NCHUNK; c++) {
        // stage prefetched registers into smem
        xs[xk + 0][xb] = xr0.x; xs[xk + 1][xb] = xr0.y;
        xs[xk + 2][xb] = xr0.z; xs[xk + 3][xb] = xr0.w;
        xs[xk + 4][xb] = xr1.x; xs[xk + 5][xb] = xr1.y;
        xs[xk + 6][xb] = xr1.z; xs[xk + 7][xb] = xr1.w;
        ws[wk + 0][wn] = wr.x;  ws[wk + 1][wn] = wr.y;
        ws[wk + 2][wn] = wr.z;  ws[wk + 3][wn] = wr.w;
        __syncthreads();

        // prefetch next chunk while computing this one
        if (c + 1 < NCHUNK) {
            const float* xp = x + xb * FDIM + (c + 1) * KC + xk;
            xr0 = *(const float4*)(xp);
            xr1 = *(const float4*)(xp + 4);
            wr  = *(const float4*)(W + (n0 + wn) * FDIM + (c + 1) * KC + wk);
        }

#pragma unroll
        for (int k = 0; k < KC; k++) {
            float w = ws[k][tx];
            unsigned long long w2;
            asm("mov.b64 %0, {%1, %1};" : "=l"(w2) : "r"(__float_as_uint(w)));
            // 8 b-rows as 4 packed pairs (two LDS.128)
            ulonglong2 a01 = *(const ulonglong2*)&xs[k][ty * 8];
            asm("fma.rn.f32x2 %0, %1, %2, %0;" : "+l"(acc[0]) : "l"(a01.x), "l"(w2));
            asm("fma.rn.f32x2 %0, %1, %2, %0;" : "+l"(acc[1]) : "l"(a01.y), "l"(w2));
            ulonglong2 a23 = *(const ulonglong2*)&xs[k][ty * 8 + 4];
            asm("fma.rn.f32x2 %0, %1, %2, %0;" : "+l"(acc[2]) : "l"(a23.x), "l"(w2));
            asm("fma.rn.f32x2 %0, %1, %2, %0;" : "+l"(acc[3]) : "l"(a23.y), "l"(w2));
        }
        __syncthreads();
    }

#pragma unroll
    for (int p = 0; p < 4; p++) {
        unsigned int lo, hi;
        asm("mov.b64 {%0, %1}, %2;" : "=r"(lo), "=r"(hi) : "l"(acc[p]));
        out[(ty * 8 + 2 * p + 0) * FDIM + n0 + tx] = __uint_as_float(lo);
        out[(ty * 8 + 2 * p + 1) * FDIM + n0 + tx] = __uint_as_float(hi);
    }
}

// ============================================================
// Phase 2: attended[b,i] = sum_j softmax_j(q_i*k_j, mask) * v_j
// block = (i-tile of 256, batch b). One thread per i.
// smem: ks[j] = mask? k : 0 ;  mv[j] = {mask?1:0, mask?v:0}
// m_i = qs>=0 ? qs*kmax : qs*kmin  (upper bound incl. 0 -> arg<=0)
// inner: t=fma(qs,ks,-m); e=ex2(t); {den,num} += {e,e}*{mf,vm}
// ============================================================
__global__ __launch_bounds__(256) void attn_kernel(
    const int* __restrict__ mask,
    float* __restrict__ out)
{
    __shared__ float  ks[FDIM];
    __shared__ float2 mv[FDIM];
    __shared__ float  red[16];

    const int b   = blockIdx.y;
    const int tid = threadIdx.x;

    const float* __restrict__ qrow = g_qkv[0] + b * FDIM;
    const float* __restrict__ krow = g_qkv[1] + b * FDIM;
    const float* __restrict__ vrow = g_qkv[2] + b * FDIM;
    const int*   __restrict__ mrow = mask + b * FDIM;

    float lmax = -1e30f, lmin = 1e30f;
    for (int j = tid; j < FDIM; j += 256) {
        int   m  = mrow[j];
        float kv = m ? krow[j] : 0.0f;
        ks[j] = kv;
        mv[j] = make_float2(m ? 1.0f : 0.0f, m ? vrow[j] : 0.0f);
        lmax = fmaxf(lmax, kv);
        lmin = fminf(lmin, kv);
    }
#pragma unroll
    for (int o = 16; o; o >>= 1) {
        lmax = fmaxf(lmax, __shfl_xor_sync(0xffffffffu, lmax, o));
        lmin = fminf(lmin, __shfl_xor_sync(0xffffffffu, lmin, o));
    }
    if ((tid & 31) == 0) { red[tid >> 5] = lmax; red[8 + (tid >> 5)] = lmin; }
    __syncthreads();

    float kmax = red[0], kmin = red[8];
#pragma unroll
    for (int w = 1; w < 8; w++) {
        kmax = fmaxf(kmax, red[w]);
        kmin = fminf(kmin, red[8 + w]);
    }

    const int i = blockIdx.x * 256 + tid;
    const float qs    = qrow[i] * LOG2E;
    const float m2    = (qs >= 0.0f) ? qs * kmax : qs * kmin;
    const float negm2 = -m2;

    unsigned long long acc = 0ull;   // {denom, numer}
    const float4*     ks4 = (const float4*)ks;
    const ulonglong2* mv2 = (const ulonglong2*)mv;

    for (int j4 = 0; j4 < FDIM / 4; j4++) {
        float4     kk = ks4[j4];
        ulonglong2 ma = mv2[2 * j4];
        ulonglong2 mb = mv2[2 * j4 + 1];

        float t0 = fmaf(qs, kk.x, negm2);
        float t1 = fmaf(qs, kk.y, negm2);
        float t2 = fmaf(qs, kk.z, negm2);
        float t3 = fmaf(qs, kk.w, negm2);
        float e0, e1, e2, e3;
        asm("ex2.approx.ftz.f32 %0, %1;" : "=f"(e0) : "f"(t0));
        asm("ex2.approx.ftz.f32 %0, %1;" : "=f"(e1) : "f"(t1));
        asm("ex2.approx.ftz.f32 %0, %1;" : "=f"(e2) : "f"(t2));
        asm("ex2.approx.ftz.f32 %0, %1;" : "=f"(e3) : "f"(t3));
        unsigned long long p0, p1, p2, p3;
        asm("mov.b64 %0, {%1, %1};" : "=l"(p0) : "r"(__float_as_uint(e0)));
        asm("mov.b64 %0, {%1, %1};" : "=l"(p1) : "r"(__float_as_uint(e1)));
        asm("mov.b64 %0, {%1, %1};" : "=l"(p2) : "r"(__float_as_uint(e2)));
        asm("mov.b64 %0, {%1, %1};" : "=l"(p3) : "r"(__float_as_uint(e3)));
        asm("fma.rn.f32x2 %0, %1, %2, %0;" : "+l"(acc) : "l"(p0), "l"(ma.x));
        asm("fma.rn.f32x2 %0, %1, %2, %0;" : "+l"(acc) : "l"(p1), "l"(ma.y));
        asm("fma.rn.f32x2 %0, %1, %2, %0;" : "+l"(acc) : "l"(p2), "l"(mb.x));
        asm("fma.rn.f32x2 %0, %1, %2, %0;" : "+l"(acc) : "l"(p3), "l"(mb.y));
    }

    unsigned int dlo, dhi;
    asm("mov.b64 {%0, %1}, %2;" : "=r"(dlo), "=r"(dhi) : "l"(acc));
    float den = __uint_as_float(dlo);
    float num = __uint_as_float(dhi);
    out[b * FDIM + i] = num / den;
}

extern "C" void kernel_launch(void* const* d_in, const int* in_sizes, int n_in,
                              void* d_out, int out_size)
{
    const float* x    = (const float*)d_in[0];
    const int*   mask = (const int*)d_in[1];
    const float* Wq   = (const float*)d_in[2];
    const float* Wk   = (const float*)d_in[3];
    const float* Wv   = (const float*)d_in[4];
    float* out = (float*)d_out;

    gemm_kernel<<<192, 256>>>(x, Wq, Wk, Wv);
    attn_kernel<<<dim3(FDIM / 256, BATCH), 256>>>(mask, out);
}

// round 3
// speedup vs baseline: 1.3716x; 1.3716x over previous
#include <cuda_runtime.h>
#include <cstdint>

#define FDIM 2048
#define BATCH 64
#define LOG2E 1.4426950408889634f

// K-split partial results: g_part[ksplit][0=q,1=k,2=v][b*F]
__device__ float g_part[3][3][BATCH * FDIM];

// ============================================================
// Phase 1: out[b,n] = sum_k x[b,k] * W[n,k]  (three weights)
// Block tile: M=64 (full batch) x N=64, K-split in 3 ranges
// (688/688/672), K-chunk 16. 256 threads, thread = 8M x 2N,
// 8 packed f32x2 accumulators -> 8 FFMA2 per k-step vs 5 aux
// instrs => fma-pipe bound. Grid 288 = ~2 blocks/SM balanced.
// ============================================================
#define KC 16
#define NT 64

__global__ __launch_bounds__(256, 2) void gemm_kernel(
    const float* __restrict__ x,
    const float* __restrict__ Wq,
    const float* __restrict__ Wk,
    const float* __restrict__ Wv)
{
    __shared__ float xs[KC][64];   // xs[k][b]
    __shared__ float ws[KC][NT];   // ws[k][n]

    const int bx   = blockIdx.x;
    const int ks   = bx % 3;               // k-split
    const int nt   = (bx / 3) & 31;        // n-tile
    const int wsel = bx / 96;              // weight
    const float* __restrict__ W = (wsel == 0) ? Wq : ((wsel == 1) ? Wk : Wv);
    float* __restrict__ out = g_part[ks][wsel];

    const int k0     = ks * 688;           // 0, 688, 1376
    const int nchunk = (ks == 2) ? 42 : 43;
    const int n0     = nt * NT;

    const int tid = threadIdx.x;
    // loader mapping (1 float4 each into xs and ws)
    const int xb = tid & 63;               // b row
    const int xk = (tid >> 6) * 4;         // k offset (4 floats along k)
    const int wn = tid & 63;               // n row
    const int wk = (tid >> 6) * 4;
    // compute mapping
    const int tx = tid & 31;               // n pair index (cols tx*2, tx*2+1)
    const int ty = tid >> 5;               // m octet (rows ty*8 .. ty*8+7)

    unsigned long long acc[8];             // [mpair 0..3][ncol 0..1]
#pragma unroll
    for (int p = 0; p < 8; p++) acc[p] = 0ull;

    float4 xr, wr;
    xr = *(const float4*)(x + xb * FDIM + k0 + xk);
    wr = *(const float4*)(W + (n0 + wn) * FDIM + k0 + wk);

    for (int c = 0; c < nchunk; c++) {
        xs[xk + 0][xb] = xr.x; xs[xk + 1][xb] = xr.y;
        xs[xk + 2][xb] = xr.z; xs[xk + 3][xb] = xr.w;
        ws[wk + 0][wn] = wr.x; ws[wk + 1][wn] = wr.y;
        ws[wk + 2][wn] = wr.z; ws[wk + 3][wn] = wr.w;
        __syncthreads();

        if (c + 1 < nchunk) {
            const int kc = k0 + (c + 1) * KC;
            xr = *(const float4*)(x + xb * FDIM + kc + xk);
            wr = *(const float4*)(W + (n0 + wn) * FDIM + kc + wk);
        }

#pragma unroll
        for (int k = 0; k < KC; k++) {
            float2 wv = *(const float2*)&ws[k][tx * 2];
            unsigned long long w0, w1;
            asm("mov.b64 %0, {%1, %1};" : "=l"(w0) : "r"(__float_as_uint(wv.x)));
            asm("mov.b64 %0, {%1, %1};" : "=l"(w1) : "r"(__float_as_uint(wv.y)));
            ulonglong2 a01 = *(const ulonglong2*)&xs[k][ty * 8];
            asm("fma.rn.f32x2 %0, %1, %2, %0;" : "+l"(acc[0]) : "l"(a01.x), "l"(w0));
            asm("fma.rn.f32x2 %0, %1, %2, %0;" : "+l"(acc[1]) : "l"(a01.x), "l"(w1));
            asm("fma.rn.f32x2 %0, %1, %2, %0;" : "+l"(acc[2]) : "l"(a01.y), "l"(w0));
            asm("fma.rn.f32x2 %0, %1, %2, %0;" : "+l"(acc[3]) : "l"(a01.y), "l"(w1));
            ulonglong2 a23 = *(const ulonglong2*)&xs[k][ty * 8 + 4];
            asm("fma.rn.f32x2 %0, %1, %2, %0;" : "+l"(acc[4]) : "l"(a23.x), "l"(w0));
            asm("fma.rn.f32x2 %0, %1, %2, %0;" : "+l"(acc[5]) : "l"(a23.x), "l"(w1));
            asm("fma.rn.f32x2 %0, %1, %2, %0;" : "+l"(acc[6]) : "l"(a23.y), "l"(w0));
            asm("fma.rn.f32x2 %0, %1, %2, %0;" : "+l"(acc[7]) : "l"(a23.y), "l"(w1));
        }
        __syncthreads();
    }

#pragma unroll
    for (int p = 0; p < 4; p++) {
#pragma unroll
        for (int cc = 0; cc < 2; cc++) {
            unsigned int lo, hi;
            asm("mov.b64 {%0, %1}, %2;" : "=r"(lo), "=r"(hi) : "l"(acc[p * 2 + cc]));
            const int n = n0 + tx * 2 + cc;
            out[(ty * 8 + 2 * p + 0) * FDIM + n] = __uint_as_float(lo);
            out[(ty * 8 + 2 * p + 1) * FDIM + n] = __uint_as_float(hi);
        }
    }
}

// ============================================================
// Phase 2: attended[b,i] = sum_j softmax_j(q_i*k_j, mask) * v_j
// q/k/v assembled from the 3 K-split partials during staging.
// smem: ks[j] = mask? k : 0 ;  mv[j] = {mask?1:0, mask?v:0}
// m_i = qs>=0 ? qs*kmax : qs*kmin  (upper bound incl. 0)
// inner: t=fma(qs,ks,-m); e=ex2(t); {den,num} += {e,e}*{mf,vm}
// ============================================================
__global__ __launch_bounds__(256) void attn_kernel(
    const int* __restrict__ mask,
    float* __restrict__ out)
{
    __shared__ float  ksm[FDIM];
    __shared__ float2 mv[FDIM];
    __shared__ float  red[16];

    const int b   = blockIdx.y;
    const int tid = threadIdx.x;
    const int off = b * FDIM;
    const int* __restrict__ mrow = mask + off;

    float lmax = -1e30f, lmin = 1e30f;
    for (int j = tid; j < FDIM; j += 256) {
        int   m  = mrow[j];
        float kv = g_part[0][1][off + j] + g_part[1][1][off + j] + g_part[2][1][off + j];
        float vv = g_part[0][2][off + j] + g_part[1][2][off + j] + g_part[2][2][off + j];
        kv = m ? kv : 0.0f;
        ksm[j] = kv;
        mv[j] = make_float2(m ? 1.0f : 0.0f, m ? vv : 0.0f);
        lmax = fmaxf(lmax, kv);
        lmin = fminf(lmin, kv);
    }
#pragma unroll
    for (int o = 16; o; o >>= 1) {
        lmax = fmaxf(lmax, __shfl_xor_sync(0xffffffffu, lmax, o));
        lmin = fminf(lmin, __shfl_xor_sync(0xffffffffu, lmin, o));
    }
    if ((tid & 31) == 0) { red[tid >> 5] = lmax; red[8 + (tid >> 5)] = lmin; }
    __syncthreads();

    float kmax = red[0], kmin = red[8];
#pragma unroll
    for (int w = 1; w < 8; w++) {
        kmax = fmaxf(kmax, red[w]);
        kmin = fminf(kmin, red[8 + w]);
    }

    const int i = blockIdx.x * 256 + tid;
    const float qraw = g_part[0][0][off + i] + g_part[1][0][off + i] + g_part[2][0][off + i];
    const float qs    = qraw * LOG2E;
    const float m2    = (qs >= 0.0f) ? qs * kmax : qs * kmin;
    const float negm2 = -m2;

    unsigned long long acc = 0ull;   // {denom, numer}
    const float4*     ks4 = (const float4*)ksm;
    const ulonglong2* mv2 = (const ulonglong2*)mv;

    for (int j4 = 0; j4 < FDIM / 4; j4++) {
        float4     kk = ks4[j4];
        ulonglong2 ma = mv2[2 * j4];
        ulonglong2 mb = mv2[2 * j4 + 1];

        float t0 = fmaf(qs, kk.x, negm2);
        float t1 = fmaf(qs, kk.y, negm2);
        float t2 = fmaf(qs, kk.z, negm2);
        float t3 = fmaf(qs, kk.w, negm2);
        float e0, e1, e2, e3;
        asm("ex2.approx.ftz.f32 %0, %1;" : "=f"(e0) : "f"(t0));
        asm("ex2.approx.ftz.f32 %0, %1;" : "=f"(e1) : "f"(t1));
        asm("ex2.approx.ftz.f32 %0, %1;" : "=f"(e2) : "f"(t2));
        asm("ex2.approx.ftz.f32 %0, %1;" : "=f"(e3) : "f"(t3));
        unsigned long long p0, p1, p2, p3;
        asm("mov.b64 %0, {%1, %1};" : "=l"(p0) : "r"(__float_as_uint(e0)));
        asm("mov.b64 %0, {%1, %1};" : "=l"(p1) : "r"(__float_as_uint(e1)));
        asm("mov.b64 %0, {%1, %1};" : "=l"(p2) : "r"(__float_as_uint(e2)));
        asm("mov.b64 %0, {%1, %1};" : "=l"(p3) : "r"(__float_as_uint(e3)));
        asm("fma.rn.f32x2 %0, %1, %2, %0;" : "+l"(acc) : "l"(p0), "l"(ma.x));
        asm("fma.rn.f32x2 %0, %1, %2, %0;" : "+l"(acc) : "l"(p1), "l"(ma.y));
        asm("fma.rn.f32x2 %0, %1, %2, %0;" : "+l"(acc) : "l"(p2), "l"(mb.x));
        asm("fma.rn.f32x2 %0, %1, %2, %0;" : "+l"(acc) : "l"(p3), "l"(mb.y));
    }

    unsigned int dlo, dhi;
    asm("mov.b64 {%0, %1}, %2;" : "=r"(dlo), "=r"(dhi) : "l"(acc));
    float den = __uint_as_float(dlo);
    float num = __uint_as_float(dhi);
    out[b * FDIM + i] = num / den;
}

extern "C" void kernel_launch(void* const* d_in, const int* in_sizes, int n_in,
                              void* d_out, int out_size)
{
    const float* x    = (const float*)d_in[0];
    const int*   mask = (const int*)d_in[1];
    const float* Wq   = (const float*)d_in[2];
    const float* Wk   = (const float*)d_in[3];
    const float* Wv   = (const float*)d_in[4];
    float* out = (float*)d_out;

    gemm_kernel<<<288, 256>>>(x, Wq, Wk, Wv);
    attn_kernel<<<dim3(FDIM / 256, BATCH), 256>>>(mask, out);
}

// round 5
// speedup vs baseline: 1.7400x; 1.2686x over previous
#include <cuda_runtime.h>
#include <cstdint>

#define FDIM 2048
#define BATCH 64
#define LOG2E 1.4426950408889634f

// K-split partial results: g_part[ksplit][0=q,1=k,2=v][b*F]
__device__ float g_part[3][3][BATCH * FDIM];

// ============================================================
// Phase 1: out[b,n] = sum_k x[b,k] * W[n,k]  (three weights)
// Block tile: M=64 (full batch) x N=64, K-split 672/672/704,
// K-chunk 32 (prefetch distance > DRAM latency). 256 threads,
// thread = 8M x 2N, 8 packed f32x2 accumulators.
// Grid 288 = ~2 blocks/SM.
// ============================================================
#define KC 32
#define NT 64

__global__ __launch_bounds__(256, 2) void gemm_kernel(
    const float* __restrict__ x,
    const float* __restrict__ Wq,
    const float* __restrict__ Wk,
    const float* __restrict__ Wv)
{
    __shared__ float xs[KC][64];   // xs[k][b]
    __shared__ float ws[KC][NT];   // ws[k][n]

    const int bx   = blockIdx.x;
    const int ks   = bx % 3;               // k-split
    const int nt   = (bx / 3) & 31;        // n-tile
    const int wsel = bx / 96;              // weight
    const float* __restrict__ W = (wsel == 0) ? Wq : ((wsel == 1) ? Wk : Wv);
    float* __restrict__ out = g_part[ks][wsel];

    const int k0     = ks * 672;           // 0, 672, 1344
    const int nchunk = (ks == 2) ? 22 : 21;
    const int n0     = nt * NT;

    const int tid = threadIdx.x;
    // loader mapping: 2 float4 into xs, 2 into ws
    const int xb = tid & 63;               // b row / n row
    const int xk = (tid >> 6) * 4;         // k offset 0,4,8,12 (+16 for 2nd)
    // compute mapping
    const int tx = tid & 31;               // n pair index
    const int ty = tid >> 5;               // m octet

    unsigned long long acc[8];
#pragma unroll
    for (int p = 0; p < 8; p++) acc[p] = 0ull;

    float4 xr0, xr1, wr0, wr1;
    {
        const float* xp = x + xb * FDIM + k0 + xk;
        xr0 = *(const float4*)(xp);
        xr1 = *(const float4*)(xp + 16);
        const float* wp = W + (n0 + xb) * FDIM + k0 + xk;
        wr0 = *(const float4*)(wp);
        wr1 = *(const float4*)(wp + 16);
    }

    for (int c = 0; c < nchunk; c++) {
        xs[xk + 0][xb] = xr0.x; xs[xk + 1][xb] = xr0.y;
        xs[xk + 2][xb] = xr0.z; xs[xk + 3][xb] = xr0.w;
        xs[xk + 16][xb] = xr1.x; xs[xk + 17][xb] = xr1.y;
        xs[xk + 18][xb] = xr1.z; xs[xk + 19][xb] = xr1.w;
        ws[xk + 0][xb] = wr0.x; ws[xk + 1][xb] = wr0.y;
        ws[xk + 2][xb] = wr0.z; ws[xk + 3][xb] = wr0.w;
        ws[xk + 16][xb] = wr1.x; ws[xk + 17][xb] = wr1.y;
        ws[xk + 18][xb] = wr1.z; ws[xk + 19][xb] = wr1.w;
        __syncthreads();

        if (c + 1 < nchunk) {
            const int kc = k0 + (c + 1) * KC;
            const float* xp = x + xb * FDIM + kc + xk;
            xr0 = *(const float4*)(xp);
            xr1 = *(const float4*)(xp + 16);
            const float* wp = W + (n0 + xb) * FDIM + kc + xk;
            wr0 = *(const float4*)(wp);
            wr1 = *(const float4*)(wp + 16);
        }

#pragma unroll
        for (int k = 0; k < KC; k++) {
            float2 wv = *(const float2*)&ws[k][tx * 2];
            unsigned long long w0, w1;
            asm("mov.b64 %0, {%1, %1};" : "=l"(w0) : "r"(__float_as_uint(wv.x)));
            asm("mov.b64 %0, {%1, %1};" : "=l"(w1) : "r"(__float_as_uint(wv.y)));
            ulonglong2 a01 = *(const ulonglong2*)&xs[k][ty * 8];
            asm("fma.rn.f32x2 %0, %1, %2, %0;" : "+l"(acc[0]) : "l"(a01.x), "l"(w0));
            asm("fma.rn.f32x2 %0, %1, %2, %0;" : "+l"(acc[1]) : "l"(a01.x), "l"(w1));
            asm("fma.rn.f32x2 %0, %1, %2, %0;" : "+l"(acc[2]) : "l"(a01.y), "l"(w0));
            asm("fma.rn.f32x2 %0, %1, %2, %0;" : "+l"(acc[3]) : "l"(a01.y), "l"(w1));
            ulonglong2 a23 = *(const ulonglong2*)&xs[k][ty * 8 + 4];
            asm("fma.rn.f32x2 %0, %1, %2, %0;" : "+l"(acc[4]) : "l"(a23.x), "l"(w0));
            asm("fma.rn.f32x2 %0, %1, %2, %0;" : "+l"(acc[5]) : "l"(a23.x), "l"(w1));
            asm("fma.rn.f32x2 %0, %1, %2, %0;" : "+l"(acc[6]) : "l"(a23.y), "l"(w0));
            asm("fma.rn.f32x2 %0, %1, %2, %0;" : "+l"(acc[7]) : "l"(a23.y), "l"(w1));
        }
        __syncthreads();
    }

#pragma unroll
    for (int p = 0; p < 4; p++) {
#pragma unroll
        for (int cc = 0; cc < 2; cc++) {
            unsigned int lo, hi;
            asm("mov.b64 {%0, %1}, %2;" : "=r"(lo), "=r"(hi) : "l"(acc[p * 2 + cc]));
            const int n = n0 + tx * 2 + cc;
            out[(ty * 8 + 2 * p + 0) * FDIM + n] = __uint_as_float(lo);
            out[(ty * 8 + 2 * p + 1) * FDIM + n] = __uint_as_float(hi);
        }
    }
}

// ============================================================
// Phase 2: attended[b,i] = softmax-weighted sum over ACTIVE j.
// Masked j contribute exactly 0 -> compact active j's in smem
// (order-free block scan), halving the MUFU.EX2 work.
// ksc[p] = k_j (active), wv[p] = {1, v_j}; pad with k=0,{0,0}.
// m = qs>=0 ? qs*kmax : qs*kmin with 0 included in k-range,
// so all exp args <= 0 (incl. padding) -> no overflow.
// ============================================================
__global__ __launch_bounds__(256) void attn_kernel(
    const int* __restrict__ mask,
    float* __restrict__ out)
{
    __shared__ float  ksc[FDIM];
    __shared__ float2 wv[FDIM];
    __shared__ float  red[16];
    __shared__ int    wsum[8];
    __shared__ int    wbase[8];

    const int b   = blockIdx.y;
    const int tid = threadIdx.x;
    const int lane = tid & 31;
    const int wid  = tid >> 5;
    const int off = b * FDIM;
    const int* __restrict__ mrow = mask + off;

    // ---- load 8 strided j's, count actives ----
    int   pr[8];
    float kvv[8], vvv[8];
    int cnt = 0;
#pragma unroll
    for (int s = 0; s < 8; s++) {
        const int j = tid + s * 256;
        const int m = mrow[j];
        kvv[s] = g_part[0][1][off + j] + g_part[1][1][off + j] + g_part[2][1][off + j];
        vvv[s] = g_part[0][2][off + j] + g_part[1][2][off + j] + g_part[2][2][off + j];
        pr[s] = m;
        cnt += m;
    }

    // ---- block exclusive scan of per-thread counts ----
    int inc = cnt;
#pragma unroll
    for (int o = 1; o < 32; o <<= 1) {
        int t = __shfl_up_sync(0xffffffffu, inc, o);
        if (lane >= o) inc += t;
    }
    if (lane == 31) wsum[wid] = inc;
    __syncthreads();
    if (tid < 8) {
        int v = wsum[tid];
#pragma unroll
        for (int o = 1; o < 8; o <<= 1) {
            int t = __shfl_up_sync(0xffu, v, o);
            if (tid >= o) v += t;
        }
        wbase[tid] = v;   // inclusive warp sums
    }
    __syncthreads();
    const int total = wbase[7];
    int pos = (wid ? wbase[wid - 1] : 0) + (inc - cnt);

    // ---- write compacted actives ----
#pragma unroll
    for (int s = 0; s < 8; s++) {
        if (pr[s]) {
            ksc[pos] = kvv[s];
            wv[pos]  = make_float2(1.0f, vvv[s]);
            pos++;
        }
    }
    const int paddedN = (total + 7) & ~7;
    for (int p = total + tid; p < paddedN; p += 256) {
        ksc[p] = 0.0f;
        wv[p]  = make_float2(0.0f, 0.0f);
    }
    __syncthreads();

    // ---- kmax/kmin over compacted (0 included via init) ----
    float lmax = 0.0f, lmin = 0.0f;
    for (int p = tid; p < paddedN; p += 256) {
        float kv = ksc[p];
        lmax = fmaxf(lmax, kv);
        lmin = fminf(lmin, kv);
    }
#pragma unroll
    for (int o = 16; o; o >>= 1) {
        lmax = fmaxf(lmax, __shfl_xor_sync(0xffffffffu, lmax, o));
        lmin = fminf(lmin, __shfl_xor_sync(0xffffffffu, lmin, o));
    }
    if (lane == 0) { red[wid] = lmax; red[8 + wid] = lmin; }
    __syncthreads();

    float kmax = red[0], kmin = red[8];
#pragma unroll
    for (int w = 1; w < 8; w++) {
        kmax = fmaxf(kmax, red[w]);
        kmin = fminf(kmin, red[8 + w]);
    }

    const int i = blockIdx.x * 256 + tid;
    const float qraw = g_part[0][0][off + i] + g_part[1][0][off + i] + g_part[2][0][off + i];
    const float qs    = qraw * LOG2E;
    const float m2    = (qs >= 0.0f) ? qs * kmax : qs * kmin;   // >= 0
    const float negm2 = -m2;

    unsigned long long accA = 0ull, accB = 0ull;   // {denom, numer}
    const float4*     ks4 = (const float4*)ksc;
    const ulonglong2* mv2 = (const ulonglong2*)wv;

    const int n4 = paddedN >> 2;
#pragma unroll 2
    for (int j4 = 0; j4 < n4; j4++) {
        float4     kk = ks4[j4];
        ulonglong2 ma = mv2[2 * j4];
        ulonglong2 mb = mv2[2 * j4 + 1];

        float t0 = fmaf(qs, kk.x, negm2);
        float t1 = fmaf(qs, kk.y, negm2);
        float t2 = fmaf(qs, kk.z, negm2);
        float t3 = fmaf(qs, kk.w, negm2);
        float e0, e1, e2, e3;
        asm("ex2.approx.ftz.f32 %0, %1;" : "=f"(e0) : "f"(t0));
        asm("ex2.approx.ftz.f32 %0, %1;" : "=f"(e1) : "f"(t1));
        asm("ex2.approx.ftz.f32 %0, %1;" : "=f"(e2) : "f"(t2));
        asm("ex2.approx.ftz.f32 %0, %1;" : "=f"(e3) : "f"(t3));
        unsigned long long p0, p1, p2, p3;
        asm("mov.b64 %0, {%1, %1};" : "=l"(p0) : "r"(__float_as_uint(e0)));
        asm("mov.b64 %0, {%1, %1};" : "=l"(p1) : "r"(__float_as_uint(e1)));
        asm("mov.b64 %0, {%1, %1};" : "=l"(p2) : "r"(__float_as_uint(e2)));
        asm("mov.b64 %0, {%1, %1};" : "=l"(p3) : "r"(__float_as_uint(e3)));
        asm("fma.rn.f32x2 %0, %1, %2, %0;" : "+l"(accA) : "l"(p0), "l"(ma.x));
        asm("fma.rn.f32x2 %0, %1, %2, %0;" : "+l"(accB) : "l"(p1), "l"(ma.y));
        asm("fma.rn.f32x2 %0, %1, %2, %0;" : "+l"(accA) : "l"(p2), "l"(mb.x));
        asm("fma.rn.f32x2 %0, %1, %2, %0;" : "+l"(accB) : "l"(p3), "l"(mb.y));
    }

    unsigned long long accT;
    asm("add.rn.f32x2 %0, %1, %2;" : "=l"(accT) : "l"(accA), "l"(accB));
    unsigned int dlo, dhi;
    asm("mov.b64 {%0, %1}, %2;" : "=r"(dlo), "=r"(dhi) : "l"(accT));
    float den = __uint_as_float(dlo);
    float num = __uint_as_float(dhi);
    out[b * FDIM + i] = num / den;
}

extern "C" void kernel_launch(void* const* d_in, const int* in_sizes, int n_in,
                              void* d_out, int out_size)
{
    const float* x    = (const float*)d_in[0];
    const int*   mask = (const int*)d_in[1];
    const float* Wq   = (const float*)d_in[2];
    const float* Wk   = (const float*)d_in[3];
    const float* Wv   = (const float*)d_in[4];
    float* out = (float*)d_out;

    gemm_kernel<<<288, 256>>>(x, Wq, Wk, Wv);
    attn_kernel<<<dim3(FDIM / 256, BATCH), 256>>>(mask, out);
}

// round 7
// speedup vs baseline: 2.9257x; 1.6815x over previous
#include <cuda_runtime.h>
#include <cstdint>

#define FDIM 2048
#define BATCH 64
#define LOG2E 1.4426950408889634f
#define NSPLIT 4

// K-split partial results: g_part[ksplit][0=q,1=k,2=v][b*F]
__device__ float g_part[NSPLIT][3][BATCH * FDIM];

#define PITCH 40   // bf16 per smem row (80B) -> conflict-free ldmatrix

// split a,b into bf16 hi pair + bf16 lo (residual) pair; a = low half
__device__ __forceinline__ void cvt_split(float a, float b, uint32_t& hi, uint32_t& lo) {
    uint32_t h;
    asm("cvt.rn.bf16x2.f32 %0, %1, %2;" : "=r"(h) : "f"(b), "f"(a));
    float ra = __uint_as_float(h << 16);
    float rb = __uint_as_float(h & 0xffff0000u);
    asm("cvt.rn.bf16x2.f32 %0, %1, %2;" : "=r"(lo) : "f"(b - rb), "f"(a - ra));
    hi = h;
}

__device__ __forceinline__ void ldsm4(uint32_t* r, uint32_t addr) {
    asm volatile("ldmatrix.sync.aligned.m8n8.x4.shared.b16 {%0,%1,%2,%3}, [%4];"
        : "=r"(r[0]), "=r"(r[1]), "=r"(r[2]), "=r"(r[3]) : "r"(addr));
}

__device__ __forceinline__ void mma16816(float* c, const uint32_t* a, uint32_t b0, uint32_t b1) {
    asm volatile("mma.sync.aligned.m16n8k16.row.col.f32.bf16.bf16.f32 "
        "{%0,%1,%2,%3}, {%4,%5,%6,%7}, {%8,%9}, {%0,%1,%2,%3};"
        : "+f"(c[0]), "+f"(c[1]), "+f"(c[2]), "+f"(c[3])
        : "r"(a[0]), "r"(a[1]), "r"(a[2]), "r"(a[3]), "r"(b0), "r"(b1));
}

// ============================================================
// Phase 1: warp-MMA GEMM, bf16 error-split (hh + hl + lh).
// out[b,n] = sum_k x[b,k]*W[n,k].  Block tile M=64 x N=64,
// K-chunk 32, K-split 4 (512 each). grid = 3*32*4 = 384.
// 8 warps = 4m x 2n, warp tile 16x32.
// ============================================================
__global__ __launch_bounds__(256, 2) void gemm_mma(
    const float* __restrict__ x,
    const float* __restrict__ Wq,
    const float* __restrict__ Wk,
    const float* __restrict__ Wv)
{
    __shared__ __align__(16) uint16_t xhi[64][PITCH];
    __shared__ __align__(16) uint16_t xlo[64][PITCH];
    __shared__ __align__(16) uint16_t whi[64][PITCH];
    __shared__ __align__(16) uint16_t wlo[64][PITCH];

    const int tid  = threadIdx.x;
    const int wid  = tid >> 5;
    const int lane = tid & 31;

    const int bx   = blockIdx.x;
    const int ks   = bx & 3;
    const int nt   = (bx >> 2) & 31;
    const int wsel = bx >> 7;
    const float* __restrict__ W = (wsel == 0) ? Wq : ((wsel == 1) ? Wk : Wv);
    float* __restrict__ outp = g_part[ks][wsel];
    const int k0 = ks * 512;
    const int n0 = nt * 64;

    const int wm = wid >> 1;     // m quarter (16 rows)
    const int wn = wid & 1;      // n half (32 cols)

    // loader mapping: 2 float4 per thread per array
    const int r0  = tid >> 3;          // 0..31  (row, +32 for j=1)
    const int c4  = tid & 7;           // float4 col within 32-k chunk

    float acc[4][4];
#pragma unroll
    for (int i = 0; i < 4; i++)
#pragma unroll
        for (int j = 0; j < 4; j++) acc[i][j] = 0.0f;

    const uint32_t xhib = (uint32_t)__cvta_generic_to_shared(xhi);
    const uint32_t xlob = (uint32_t)__cvta_generic_to_shared(xlo);
    const uint32_t whib = (uint32_t)__cvta_generic_to_shared(whi);
    const uint32_t wlob = (uint32_t)__cvta_generic_to_shared(wlo);

    // ldmatrix addresses
    const uint32_t a_off = (uint32_t)((wm * 16 + (lane & 15)) * PITCH + (lane >> 4) * 8) * 2;
    const int brow = wn * 32 + ((lane >> 4) << 3) + (lane & 7);
    const uint32_t b_off = (uint32_t)(brow * PITCH + ((lane >> 3) & 1) * 8) * 2;

    float4 xr0, xr1, wr0, wr1;
    {
        const float* xp = x + r0 * FDIM + k0 + c4 * 4;
        xr0 = *(const float4*)(xp);
        xr1 = *(const float4*)(xp + 32 * FDIM);
        const float* wp = W + (n0 + r0) * FDIM + k0 + c4 * 4;
        wr0 = *(const float4*)(wp);
        wr1 = *(const float4*)(wp + 32 * FDIM);
    }

    for (int c = 0; c < 16; c++) {
        __syncthreads();   // previous chunk's ldmatrix done

        // convert + store staged registers
        {
            uint32_t h01, l01, h23, l23;
            cvt_split(xr0.x, xr0.y, h01, l01);
            cvt_split(xr0.z, xr0.w, h23, l23);
            *(uint2*)&xhi[r0][c4 * 4] = make_uint2(h01, h23);
            *(uint2*)&xlo[r0][c4 * 4] = make_uint2(l01, l23);
            cvt_split(xr1.x, xr1.y, h01, l01);
            cvt_split(xr1.z, xr1.w, h23, l23);
            *(uint2*)&xhi[r0 + 32][c4 * 4] = make_uint2(h01, h23);
            *(uint2*)&xlo[r0 + 32][c4 * 4] = make_uint2(l01, l23);
            cvt_split(wr0.x, wr0.y, h01, l01);
            cvt_split(wr0.z, wr0.w, h23, l23);
            *(uint2*)&whi[r0][c4 * 4] = make_uint2(h01, h23);
            *(uint2*)&wlo[r0][c4 * 4] = make_uint2(l01, l23);
            cvt_split(wr1.x, wr1.y, h01, l01);
            cvt_split(wr1.z, wr1.w, h23, l23);
            *(uint2*)&whi[r0 + 32][c4 * 4] = make_uint2(h01, h23);
            *(uint2*)&wlo[r0 + 32][c4 * 4] = make_uint2(l01, l23);
        }

        // prefetch next chunk (overlaps with MMA below)
        if (c + 1 < 16) {
            const int kb = k0 + (c + 1) * 32;
            const float* xp = x + r0 * FDIM + kb + c4 * 4;
            xr0 = *(const float4*)(xp);
            xr1 = *(const float4*)(xp + 32 * FDIM);
            const float* wp = W + (n0 + r0) * FDIM + kb + c4 * 4;
            wr0 = *(const float4*)(wp);
            wr1 = *(const float4*)(wp + 32 * FDIM);
        }
        __syncthreads();

#pragma unroll
        for (int kstep = 0; kstep < 2; kstep++) {
            const uint32_t kb = kstep * 32;   // 16 bf16 = 32 bytes
            uint32_t ah[4], al[4], bh0[4], bh1[4], bl0[4], bl1[4];
            ldsm4(ah,  xhib + a_off + kb);
            ldsm4(al,  xlob + a_off + kb);
            ldsm4(bh0, whib + b_off + kb);
            ldsm4(bh1, whib + b_off + 16 * PITCH * 2 + kb);
            ldsm4(bl0, wlob + b_off + kb);
            ldsm4(bl1, wlob + b_off + 16 * PITCH * 2 + kb);

            // hh
            mma16816(acc[0], ah, bh0[0], bh0[1]);
            mma16816(acc[1], ah, bh0[2], bh0[3]);
            mma16816(acc[2], ah, bh1[0], bh1[1]);
            mma16816(acc[3], ah, bh1[2], bh1[3]);
            // hl
            mma16816(acc[0], ah, bl0[0], bl0[1]);
            mma16816(acc[1], ah, bl0[2], bl0[3]);
            mma16816(acc[2], ah, bl1[0], bl1[1]);
            mma16816(acc[3], ah, bl1[2], bl1[3]);
            // lh
            mma16816(acc[0], al, bh0[0], bh0[1]);
            mma16816(acc[1], al, bh0[2], bh0[3]);
            mma16816(acc[2], al, bh1[0], bh1[1]);
            mma16816(acc[3], al, bh1[2], bh1[3]);
        }
    }

    // epilogue: c0,c1 -> row, c2,c3 -> row+8
    const int orow = wm * 16 + (lane >> 2);
    const int ocol = n0 + wn * 32 + (lane & 3) * 2;
#pragma unroll
    for (int t = 0; t < 4; t++) {
        const int col = ocol + t * 8;
        *(float2*)&outp[orow * FDIM + col]       = make_float2(acc[t][0], acc[t][1]);
        *(float2*)&outp[(orow + 8) * FDIM + col] = make_float2(acc[t][2], acc[t][3]);
    }
}

// ============================================================
// Phase 2: attended[b,i] = softmax-weighted sum over ACTIVE j.
// Compacted active j's (order-free), 4-way partial sums.
// ============================================================
__global__ __launch_bounds__(256) void attn_kernel(
    const int* __restrict__ mask,
    float* __restrict__ out)
{
    __shared__ float  ksc[FDIM];
    __shared__ float2 wv[FDIM];
    __shared__ float  red[16];
    __shared__ int    wsum[8];
    __shared__ int    wbase[8];

    const int b    = blockIdx.y;
    const int tid  = threadIdx.x;
    const int lane = tid & 31;
    const int wid  = tid >> 5;
    const int off  = b * FDIM;
    const int* __restrict__ mrow = mask + off;

    int   pr[8];
    float kvv[8], vvv[8];
    int cnt = 0;
#pragma unroll
    for (int s = 0; s < 8; s++) {
        const int j = tid + s * 256;
        const int m = mrow[j];
        float kv = 0.0f, vv = 0.0f;
#pragma unroll
        for (int sp = 0; sp < NSPLIT; sp++) {
            kv += g_part[sp][1][off + j];
            vv += g_part[sp][2][off + j];
        }
        kvv[s] = kv; vvv[s] = vv;
        pr[s] = m;
        cnt += m;
    }

    int inc = cnt;
#pragma unroll
    for (int o = 1; o < 32; o <<= 1) {
        int t = __shfl_up_sync(0xffffffffu, inc, o);
        if (lane >= o) inc += t;
    }
    if (lane == 31) wsum[wid] = inc;
    __syncthreads();
    if (tid < 8) {
        int v = wsum[tid];
#pragma unroll
        for (int o = 1; o < 8; o <<= 1) {
            int t = __shfl_up_sync(0xffu, v, o);
            if (tid >= o) v += t;
        }
        wbase[tid] = v;
    }
    __syncthreads();
    const int total = wbase[7];
    int pos = (wid ? wbase[wid - 1] : 0) + (inc - cnt);

#pragma unroll
    for (int s = 0; s < 8; s++) {
        if (pr[s]) {
            ksc[pos] = kvv[s];
            wv[pos]  = make_float2(1.0f, vvv[s]);
            pos++;
        }
    }
    const int paddedN = (total + 7) & ~7;
    for (int p = total + tid; p < paddedN; p += 256) {
        ksc[p] = 0.0f;
        wv[p]  = make_float2(0.0f, 0.0f);
    }
    __syncthreads();

    float lmax = 0.0f, lmin = 0.0f;
    for (int p = tid; p < paddedN; p += 256) {
        float kv = ksc[p];
        lmax = fmaxf(lmax, kv);
        lmin = fminf(lmin, kv);
    }
#pragma unroll
    for (int o = 16; o; o >>= 1) {
        lmax = fmaxf(lmax, __shfl_xor_sync(0xffffffffu, lmax, o));
        lmin = fminf(lmin, __shfl_xor_sync(0xffffffffu, lmin, o));
    }
    if (lane == 0) { red[wid] = lmax; red[8 + wid] = lmin; }
    __syncthreads();

    float kmax = red[0], kmin = red[8];
#pragma unroll
    for (int w = 1; w < 8; w++) {
        kmax = fmaxf(kmax, red[w]);
        kmin = fminf(kmin, red[8 + w]);
    }

    const int i = blockIdx.x * 256 + tid;
    float qraw = 0.0f;
#pragma unroll
    for (int sp = 0; sp < NSPLIT; sp++) qraw += g_part[sp][0][off + i];
    const float qs    = qraw * LOG2E;
    const float m2    = (qs >= 0.0f) ? qs * kmax : qs * kmin;
    const float negm2 = -m2;

    unsigned long long accA = 0ull, accB = 0ull;
    const float4*     ks4 = (const float4*)ksc;
    const ulonglong2* mv2 = (const ulonglong2*)wv;

    const int n4 = paddedN >> 2;
#pragma unroll 2
    for (int j4 = 0; j4 < n4; j4++) {
        float4     kk = ks4[j4];
        ulonglong2 ma = mv2[2 * j4];
        ulonglong2 mb = mv2[2 * j4 + 1];

        float t0 = fmaf(qs, kk.x, negm2);
        float t1 = fmaf(qs, kk.y, negm2);
        float t2 = fmaf(qs, kk.z, negm2);
        float t3 = fmaf(qs, kk.w, negm2);
        float e0, e1, e2, e3;
        asm("ex2.approx.ftz.f32 %0, %1;" : "=f"(e0) : "f"(t0));
        asm("ex2.approx.ftz.f32 %0, %1;" : "=f"(e1) : "f"(t1));
        asm("ex2.approx.ftz.f32 %0, %1;" : "=f"(e2) : "f"(t2));
        asm("ex2.approx.ftz.f32 %0, %1;" : "=f"(e3) : "f"(t3));
        unsigned long long p0, p1, p2, p3;
        asm("mov.b64 %0, {%1, %1};" : "=l"(p0) : "r"(__float_as_uint(e0)));
        asm("mov.b64 %0, {%1, %1};" : "=l"(p1) : "r"(__float_as_uint(e1)));
        asm("mov.b64 %0, {%1, %1};" : "=l"(p2) : "r"(__float_as_uint(e2)));
        asm("mov.b64 %0, {%1, %1};" : "=l"(p3) : "r"(__float_as_uint(e3)));
        asm("fma.rn.f32x2 %0, %1, %2, %0;" : "+l"(accA) : "l"(p0), "l"(ma.x));
        asm("fma.rn.f32x2 %0, %1, %2, %0;" : "+l"(accB) : "l"(p1), "l"(ma.y));
        asm("fma.rn.f32x2 %0, %1, %2, %0;" : "+l"(accA) : "l"(p2), "l"(mb.x));
        asm("fma.rn.f32x2 %0, %1, %2, %0;" : "+l"(accB) : "l"(p3), "l"(mb.y));
    }

    unsigned long long accT;
    asm("add.rn.f32x2 %0, %1, %2;" : "=l"(accT) : "l"(accA), "l"(accB));
    unsigned int dlo, dhi;
    asm("mov.b64 {%0, %1}, %2;" : "=r"(dlo), "=r"(dhi) : "l"(accT));
    float den = __uint_as_float(dlo);
    float num = __uint_as_float(dhi);
    out[b * FDIM + i] = num / den;
}

extern "C" void kernel_launch(void* const* d_in, const int* in_sizes, int n_in,
                              void* d_out, int out_size)
{
    const float* x    = (const float*)d_in[0];
    const int*   mask = (const int*)d_in[1];
    const float* Wq   = (const float*)d_in[2];
    const float* Wk   = (const float*)d_in[3];
    const float* Wv   = (const float*)d_in[4];
    float* out = (float*)d_out;

    gemm_mma<<<384, 256>>>(x, Wq, Wk, Wv);
    attn_kernel<<<dim3(FDIM / 256, BATCH), 256>>>(mask, out);
}

// round 8
// speedup vs baseline: 3.1388x; 1.0728x over previous
#include <cuda_runtime.h>
#include <cstdint>

#define FDIM 2048
#define BATCH 64
#define LOG2E 1.4426950408889634f
#define NSPLIT 4
#define NBINS 160
#define C1T 0.69314718056f     // ln2
#define C2T 0.24022650696f     // ln2^2/2
#define C3T 0.05550410866f     // ln2^3/6

// K-split partial results: g_part[ksplit][0=q,1=k,2=v][b*F]
__device__ float g_part[NSPLIT][3][BATCH * FDIM];

// bin tables
__device__ float  g_binK[BATCH][NBINS];
__device__ float4 g_binA[BATCH][NBINS];   // {S0d,S0n,S1d,S1n}
__device__ float4 g_binB[BATCH][NBINS];   // {S2d,S2n,S3d,S3n}
__device__ int    g_nb[BATCH];
__device__ float2 g_kext[BATCH];          // {kmax', kmin'} (0 included)

#define PITCH 40   // bf16 per smem row (80B) -> conflict-free ldmatrix

// split a,b into bf16 hi pair + bf16 lo (residual) pair; a = low half
__device__ __forceinline__ void cvt_split(float a, float b, uint32_t& hi, uint32_t& lo) {
    uint32_t h;
    asm("cvt.rn.bf16x2.f32 %0, %1, %2;" : "=r"(h) : "f"(b), "f"(a));
    float ra = __uint_as_float(h << 16);
    float rb = __uint_as_float(h & 0xffff0000u);
    asm("cvt.rn.bf16x2.f32 %0, %1, %2;" : "=r"(lo) : "f"(b - rb), "f"(a - ra));
    hi = h;
}

__device__ __forceinline__ void ldsm4(uint32_t* r, uint32_t addr) {
    asm volatile("ldmatrix.sync.aligned.m8n8.x4.shared.b16 {%0,%1,%2,%3}, [%4];"
        : "=r"(r[0]), "=r"(r[1]), "=r"(r[2]), "=r"(r[3]) : "r"(addr));
}

__device__ __forceinline__ void mma16816(float* c, const uint32_t* a, uint32_t b0, uint32_t b1) {
    asm volatile("mma.sync.aligned.m16n8k16.row.col.f32.bf16.bf16.f32 "
        "{%0,%1,%2,%3}, {%4,%5,%6,%7}, {%8,%9}, {%0,%1,%2,%3};"
        : "+f"(c[0]), "+f"(c[1]), "+f"(c[2]), "+f"(c[3])
        : "r"(a[0]), "r"(a[1]), "r"(a[2]), "r"(a[3]), "r"(b0), "r"(b1));
}

// ============================================================
// Phase 1: warp-MMA GEMM, bf16 error-split (hh + hl + lh).
// (unchanged from R7)
// ============================================================
__global__ __launch_bounds__(256, 2) void gemm_mma(
    const float* __restrict__ x,
    const float* __restrict__ Wq,
    const float* __restrict__ Wk,
    const float* __restrict__ Wv)
{
    __shared__ __align__(16) uint16_t xhi[64][PITCH];
    __shared__ __align__(16) uint16_t xlo[64][PITCH];
    __shared__ __align__(16) uint16_t whi[64][PITCH];
    __shared__ __align__(16) uint16_t wlo[64][PITCH];

    const int tid  = threadIdx.x;
    const int wid  = tid >> 5;
    const int lane = tid & 31;

    const int bx   = blockIdx.x;
    const int ks   = bx & 3;
    const int nt   = (bx >> 2) & 31;
    const int wsel = bx >> 7;
    const float* __restrict__ W = (wsel == 0) ? Wq : ((wsel == 1) ? Wk : Wv);
    float* __restrict__ outp = g_part[ks][wsel];
    const int k0 = ks * 512;
    const int n0 = nt * 64;

    const int wm = wid >> 1;
    const int wn = wid & 1;
    const int r0  = tid >> 3;
    const int c4  = tid & 7;

    float acc[4][4];
#pragma unroll
    for (int i = 0; i < 4; i++)
#pragma unroll
        for (int j = 0; j < 4; j++) acc[i][j] = 0.0f;

    const uint32_t xhib = (uint32_t)__cvta_generic_to_shared(xhi);
    const uint32_t xlob = (uint32_t)__cvta_generic_to_shared(xlo);
    const uint32_t whib = (uint32_t)__cvta_generic_to_shared(whi);
    const uint32_t wlob = (uint32_t)__cvta_generic_to_shared(wlo);

    const uint32_t a_off = (uint32_t)((wm * 16 + (lane & 15)) * PITCH + (lane >> 4) * 8) * 2;
    const int brow = wn * 32 + ((lane >> 4) << 3) + (lane & 7);
    const uint32_t b_off = (uint32_t)(brow * PITCH + ((lane >> 3) & 1) * 8) * 2;

    float4 xr0, xr1, wr0, wr1;
    {
        const float* xp = x + r0 * FDIM + k0 + c4 * 4;
        xr0 = *(const float4*)(xp);
        xr1 = *(const float4*)(xp + 32 * FDIM);
        const float* wp = W + (n0 + r0) * FDIM + k0 + c4 * 4;
        wr0 = *(const float4*)(wp);
        wr1 = *(const float4*)(wp + 32 * FDIM);
    }

    for (int c = 0; c < 16; c++) {
        __syncthreads();
        {
            uint32_t h01, l01, h23, l23;
            cvt_split(xr0.x, xr0.y, h01, l01);
            cvt_split(xr0.z, xr0.w, h23, l23);
            *(uint2*)&xhi[r0][c4 * 4] = make_uint2(h01, h23);
            *(uint2*)&xlo[r0][c4 * 4] = make_uint2(l01, l23);
            cvt_split(xr1.x, xr1.y, h01, l01);
            cvt_split(xr1.z, xr1.w, h23, l23);
            *(uint2*)&xhi[r0 + 32][c4 * 4] = make_uint2(h01, h23);
            *(uint2*)&xlo[r0 + 32][c4 * 4] = make_uint2(l01, l23);
            cvt_split(wr0.x, wr0.y, h01, l01);
            cvt_split(wr0.z, wr0.w, h23, l23);
            *(uint2*)&whi[r0][c4 * 4] = make_uint2(h01, h23);
            *(uint2*)&wlo[r0][c4 * 4] = make_uint2(l01, l23);
            cvt_split(wr1.x, wr1.y, h01, l01);
            cvt_split(wr1.z, wr1.w, h23, l23);
            *(uint2*)&whi[r0 + 32][c4 * 4] = make_uint2(h01, h23);
            *(uint2*)&wlo[r0 + 32][c4 * 4] = make_uint2(l01, l23);
        }

        if (c + 1 < 16) {
            const int kb = k0 + (c + 1) * 32;
            const float* xp = x + r0 * FDIM + kb + c4 * 4;
            xr0 = *(const float4*)(xp);
            xr1 = *(const float4*)(xp + 32 * FDIM);
            const float* wp = W + (n0 + r0) * FDIM + kb + c4 * 4;
            wr0 = *(const float4*)(wp);
            wr1 = *(const float4*)(wp + 32 * FDIM);
        }
        __syncthreads();

#pragma unroll
        for (int kstep = 0; kstep < 2; kstep++) {
            const uint32_t kb = kstep * 32;
            uint32_t ah[4], al[4], bh0[4], bh1[4], bl0[4], bl1[4];
            ldsm4(ah,  xhib + a_off + kb);
            ldsm4(al,  xlob + a_off + kb);
            ldsm4(bh0, whib + b_off + kb);
            ldsm4(bh1, whib + b_off + 16 * PITCH * 2 + kb);
            ldsm4(bl0, wlob + b_off + kb);
            ldsm4(bl1, wlob + b_off + 16 * PITCH * 2 + kb);

            mma16816(acc[0], ah, bh0[0], bh0[1]);
            mma16816(acc[1], ah, bh0[2], bh0[3]);
            mma16816(acc[2], ah, bh1[0], bh1[1]);
            mma16816(acc[3], ah, bh1[2], bh1[3]);
            mma16816(acc[0], ah, bl0[0], bl0[1]);
            mma16816(acc[1], ah, bl0[2], bl0[3]);
            mma16816(acc[2], ah, bl1[0], bl1[1]);
            mma16816(acc[3], ah, bl1[2], bl1[3]);
            mma16816(acc[0], al, bh0[0], bh0[1]);
            mma16816(acc[1], al, bh0[2], bh0[3]);
            mma16816(acc[2], al, bh1[0], bh1[1]);
            mma16816(acc[3], al, bh1[2], bh1[3]);
        }
    }

    const int orow = wm * 16 + (lane >> 2);
    const int ocol = n0 + wn * 32 + (lane & 3) * 2;
#pragma unroll
    for (int t = 0; t < 4; t++) {
        const int col = ocol + t * 8;
        *(float2*)&outp[orow * FDIM + col]       = make_float2(acc[t][0], acc[t][1]);
        *(float2*)&outp[(orow + 8) * FDIM + col] = make_float2(acc[t][2], acc[t][3]);
    }
}

// ============================================================
// Phase 2a: per-batch bin tables. grid = 64 (one block per b).
// Bins over active k range; per-bin Taylor moments S0..S3 for
// {den, num} with ln2^n/n! folded in. Compacted to non-empty.
// ============================================================
__global__ __launch_bounds__(256) void binprep(const int* __restrict__ mask)
{
    __shared__ float  skk[FDIM];
    __shared__ float  svv[FDIM];
    __shared__ unsigned char sact[FDIM];
    __shared__ __align__(16) float4 sA[NBINS];
    __shared__ __align__(16) float4 sB[NBINS];
    __shared__ float red[16];
    __shared__ int   wsum[8];
    __shared__ int   wbase[8];
    __shared__ float sext[2];

    const int b    = blockIdx.x;
    const int tid  = threadIdx.x;
    const int lane = tid & 31;
    const int wid  = tid >> 5;
    const int off  = b * FDIM;
    const int* __restrict__ mrow = mask + off;

    float lmax = 0.0f, lmin = 0.0f;   // include 0
#pragma unroll
    for (int s = 0; s < 8; s++) {
        const int j = tid + s * 256;
        const int m = mrow[j];
        float kv = 0.0f, vv = 0.0f;
#pragma unroll
        for (int sp = 0; sp < NSPLIT; sp++) {
            kv += g_part[sp][1][off + j];
            vv += g_part[sp][2][off + j];
        }
        skk[j] = kv; svv[j] = vv; sact[j] = (unsigned char)m;
        if (m) { lmax = fmaxf(lmax, kv); lmin = fminf(lmin, kv); }
    }
#pragma unroll
    for (int o = 16; o; o >>= 1) {
        lmax = fmaxf(lmax, __shfl_xor_sync(0xffffffffu, lmax, o));
        lmin = fminf(lmin, __shfl_xor_sync(0xffffffffu, lmin, o));
    }
    if (lane == 0) { red[wid] = lmax; red[8 + wid] = lmin; }
    // zero bins
    if (tid < NBINS) {
        sA[tid] = make_float4(0.f, 0.f, 0.f, 0.f);
        sB[tid] = make_float4(0.f, 0.f, 0.f, 0.f);
    }
    __syncthreads();

    float kmax = red[0], kmin = red[8];
#pragma unroll
    for (int w = 1; w < 8; w++) {
        kmax = fmaxf(kmax, red[w]);
        kmin = fminf(kmin, red[8 + w]);
    }
    const float range = fmaxf(kmax - kmin, 1e-12f);
    const float dlt   = range / NBINS;
    const float invd  = NBINS / range;

    // scatter
#pragma unroll
    for (int s = 0; s < 8; s++) {
        const int j = tid + s * 256;
        if (sact[j]) {
            const float k = skk[j];
            const float v = svv[j];
            int bi = (int)((k - kmin) * invd);
            bi = bi < 0 ? 0 : (bi > NBINS - 1 ? NBINS - 1 : bi);
            const float d  = k - (kmin + (bi + 0.5f) * dlt);
            const float d1 = C1T * d;
            const float d2 = C2T * d * d;
            const float d3 = C3T * d * d * d;
            atomicAdd(&sA[bi].x, 1.0f);
            atomicAdd(&sA[bi].y, v);
            atomicAdd(&sA[bi].z, d1);
            atomicAdd(&sA[bi].w, d1 * v);
            atomicAdd(&sB[bi].x, d2);
            atomicAdd(&sB[bi].y, d2 * v);
            atomicAdd(&sB[bi].z, d3);
            atomicAdd(&sB[bi].w, d3 * v);
        }
    }
    __syncthreads();

    // compact non-empty bins
    const int flag = (tid < NBINS) && (sA[tid].x > 0.0f);
    int inc = flag;
#pragma unroll
    for (int o = 1; o < 32; o <<= 1) {
        int t = __shfl_up_sync(0xffffffffu, inc, o);
        if (lane >= o) inc += t;
    }
    if (lane == 31) wsum[wid] = inc;
    __syncthreads();
    if (tid < 8) {
        int v = wsum[tid];
#pragma unroll
        for (int o = 1; o < 8; o <<= 1) {
            int t = __shfl_up_sync(0xffu, v, o);
            if (tid >= o) v += t;
        }
        wbase[tid] = v;
    }
    __syncthreads();
    const int total = wbase[7];
    const int nbPad = (total + 3) & ~3;
    if (flag) {
        const int slot = (wid ? wbase[wid - 1] : 0) + inc - 1;
        g_binK[b][slot] = kmin + (tid + 0.5f) * dlt;
        g_binA[b][slot] = sA[tid];
        g_binB[b][slot] = sB[tid];
    }
    if (tid >= total && tid < nbPad) {
        g_binK[b][tid] = 0.0f;
        g_binA[b][tid] = make_float4(0.f, 0.f, 0.f, 0.f);
        g_binB[b][tid] = make_float4(0.f, 0.f, 0.f, 0.f);
    }
    if (tid == 0) {
        g_nb[b] = nbPad;
        g_kext[b] = make_float2(kmax, kmin);   // already include 0
    }
}

// ============================================================
// Phase 2b: attended[b,i] via bin tables. grid (8, 64).
// Per bin: e = 2^(qs*kc - m); P = S0+qs*S1+qs^2*S2+qs^3*S3;
// {den,num} += e * P   (packed f32x2).
// ============================================================
__global__ __launch_bounds__(256) void attn2(float* __restrict__ out)
{
    __shared__ float sK[NBINS];
    __shared__ __align__(16) float4 sAA[NBINS];
    __shared__ __align__(16) float4 sBB[NBINS];

    const int b   = blockIdx.y;
    const int tid = threadIdx.x;
    const int off = b * FDIM;

    const int    nb = g_nb[b];
    const float2 ke = g_kext[b];

    for (int t = tid; t < nb; t += 256) {
        sK[t]  = g_binK[b][t];
        sAA[t] = g_binA[b][t];
        sBB[t] = g_binB[b][t];
    }
    __syncthreads();

    const int i = blockIdx.x * 256 + tid;
    float qraw = 0.0f;
#pragma unroll
    for (int sp = 0; sp < NSPLIT; sp++) qraw += g_part[sp][0][off + i];
    const float qs   = qraw * LOG2E;
    const float m2   = (qs >= 0.0f) ? qs * ke.x : qs * ke.y;
    const float negm = -m2;
    unsigned long long qs2;
    asm("mov.b64 %0, {%1, %1};" : "=l"(qs2) : "r"(__float_as_uint(qs)));

    unsigned long long acc = 0ull;

#pragma unroll 2
    for (int p = 0; p < nb; p++) {
        const float kc = sK[p];
        ulonglong2 A = *(const ulonglong2*)&sAA[p];
        ulonglong2 B = *(const ulonglong2*)&sBB[p];
        float t = fmaf(qs, kc, negm);
        float e;
        asm("ex2.approx.ftz.f32 %0, %1;" : "=f"(e) : "f"(t));
        unsigned long long e2, H;
        asm("mov.b64 %0, {%1, %1};" : "=l"(e2) : "r"(__float_as_uint(e)));
        asm("fma.rn.f32x2 %0, %1, %2, %3;" : "=l"(H) : "l"(qs2), "l"(B.y), "l"(B.x));
        asm("fma.rn.f32x2 %0, %1, %2, %3;" : "=l"(H) : "l"(qs2), "l"(H), "l"(A.y));
        asm("fma.rn.f32x2 %0, %1, %2, %3;" : "=l"(H) : "l"(qs2), "l"(H), "l"(A.x));
        asm("fma.rn.f32x2 %0, %1, %2, %0;" : "+l"(acc) : "l"(e2), "l"(H));
    }

    unsigned int dlo, dhi;
    asm("mov.b64 {%0, %1}, %2;" : "=r"(dlo), "=r"(dhi) : "l"(acc));
    out[off + i] = __uint_as_float(dhi) / __uint_as_float(dlo);
}

extern "C" void kernel_launch(void* const* d_in, const int* in_sizes, int n_in,
                              void* d_out, int out_size)
{
    const float* x    = (const float*)d_in[0];
    const int*   mask = (const int*)d_in[1];
    const float* Wq   = (const float*)d_in[2];
    const float* Wk   = (const float*)d_in[3];
    const float* Wv   = (const float*)d_in[4];
    float* out = (float*)d_out;

    gemm_mma<<<384, 256>>>(x, Wq, Wk, Wv);
    binprep<<<BATCH, 256>>>(mask);
    attn2<<<dim3(FDIM / 256, BATCH), 256>>>(out);
}

// round 9
// speedup vs baseline: 3.3874x; 1.0792x over previous
#include <cuda_runtime.h>
#include <cstdint>

#define FDIM 2048
#define BATCH 64
#define LOG2E 1.4426950408889634f
#define NSPLIT 4
#define NBINS 160
#define C1T 0.69314718056f     // ln2
#define C2T 0.24022650696f     // ln2^2/2
#define C3T 0.05550410866f     // ln2^3/6

// K-split partial results: g_part[ksplit][0=q,1=k,2=v][b*F]
__device__ float g_part[NSPLIT][3][BATCH * FDIM];

// bin tables
__device__ float  g_binK[BATCH][NBINS];
__device__ float4 g_binA[BATCH][NBINS];   // {S0d,S0n,S1d,S1n}
__device__ float4 g_binB[BATCH][NBINS];   // {S2d,S2n,S3d,S3n}
__device__ int    g_nb[BATCH];
__device__ float2 g_kext[BATCH];          // {kmax', kmin'} (0 included)

// split a,b into bf16 hi pair + bf16 lo (residual) pair; a = low half
__device__ __forceinline__ void cvt_split(float a, float b, uint32_t& hi, uint32_t& lo) {
    uint32_t h;
    asm("cvt.rn.bf16x2.f32 %0, %1, %2;" : "=r"(h) : "f"(b), "f"(a));
    float ra = __uint_as_float(h << 16);
    float rb = __uint_as_float(h & 0xffff0000u);
    asm("cvt.rn.bf16x2.f32 %0, %1, %2;" : "=r"(lo) : "f"(b - rb), "f"(a - ra));
    hi = h;
}

__device__ __forceinline__ void mma16816(float* c, const uint32_t* a, uint32_t b0, uint32_t b1) {
    asm volatile("mma.sync.aligned.m16n8k16.row.col.f32.bf16.bf16.f32 "
        "{%0,%1,%2,%3}, {%4,%5,%6,%7}, {%8,%9}, {%0,%1,%2,%3};"
        : "+f"(c[0]), "+f"(c[1]), "+f"(c[2]), "+f"(c[3])
        : "r"(a[0]), "r"(a[1]), "r"(a[2]), "r"(a[3]), "r"(b0), "r"(b1));
}

__device__ __forceinline__ void cpa16(uint32_t dst, const void* src) {
    asm volatile("cp.async.cg.shared.global [%0], [%1], 16;" :: "r"(dst), "l"(src));
}

// ============================================================
// Phase 1: warp-MMA GEMM, bf16 error-split (hh + hl + lh),
// 3-stage cp.async pipeline of raw fp32 tiles; fragments
// assembled by direct LDS.128 + in-register convert (shared
// k-permutation between A and B makes each fragment one LDS).
// Block tile M=64 x N=64, K-chunk 32, K-split 4. grid 384.
// ============================================================
#define SPITCH 48                      // fp32 per smem row (192B = 64 mod 128)
#define STG_ARR (64 * SPITCH * 4)      // 12288 B per array per stage
#define STG_PAIR (2 * STG_ARR)         // 24576 B per stage
#define NSTAGE 3
#define GEMM_SMEM (NSTAGE * STG_PAIR)  // 73728 B

__global__ __launch_bounds__(256, 2) void gemm_mma(
    const float* __restrict__ x,
    const float* __restrict__ Wq,
    const float* __restrict__ Wk,
    const float* __restrict__ Wv)
{
    extern __shared__ char smem[];
    const uint32_t sb = (uint32_t)__cvta_generic_to_shared(smem);

    const int tid  = threadIdx.x;
    const int wid  = tid >> 5;
    const int lane = tid & 31;

    const int bx   = blockIdx.x;
    const int ks   = bx & 3;
    const int nt   = (bx >> 2) & 31;
    const int wsel = bx >> 7;
    const float* __restrict__ W = (wsel == 0) ? Wq : ((wsel == 1) ? Wk : Wv);
    float* __restrict__ outp = g_part[ks][wsel];
    const int k0 = ks * 512;
    const int n0 = nt * 64;

    const int wm = wid >> 1;           // m quarter
    const int wn = wid & 1;            // n half
    const int gid  = lane >> 2;
    const int tidq = lane & 3;

    // cp.async loader mapping: 2 rows per thread per array
    const int lrow = tid >> 3;         // 0..31 (+32 for second)
    const int lc16 = tid & 7;          // 16B col within 128B row-chunk
    const float* xsrc0 = x + lrow * FDIM + k0 + lc16 * 4;
    const float* xsrc1 = xsrc0 + 32 * FDIM;
    const float* wsrc0 = W + (n0 + lrow) * FDIM + k0 + lc16 * 4;
    const float* wsrc1 = wsrc0 + 32 * FDIM;
    const uint32_t xdst0 = sb + lrow * 192 + lc16 * 16;
    const uint32_t xdst1 = xdst0 + 32 * 192;
    const uint32_t wdst0 = xdst0 + STG_ARR;
    const uint32_t wdst1 = wdst0 + 32 * 192;

    float acc[4][4];
#pragma unroll
    for (int i = 0; i < 4; i++)
#pragma unroll
        for (int j = 0; j < 4; j++) acc[i][j] = 0.0f;

    // fragment LDS addresses (within a stage)
    const uint32_t a_base = (uint32_t)((wm * 16 + gid) * 192 + tidq * 16);
    const uint32_t b_base = (uint32_t)(STG_ARR + (wn * 32 + gid) * 192 + tidq * 16);

    // prologue: stages 0,1 = chunks 0,1
#pragma unroll
    for (int pc = 0; pc < NSTAGE - 1; pc++) {
        const uint32_t so = pc * STG_PAIR;
        const int kf = pc * 32;
        cpa16(so + xdst0, xsrc0 + kf);
        cpa16(so + xdst1, xsrc1 + kf);
        cpa16(so + wdst0, wsrc0 + kf);
        cpa16(so + wdst1, wsrc1 + kf);
        asm volatile("cp.async.commit_group;" ::: "memory");
    }

    for (int c = 0; c < 16; c++) {
        asm volatile("cp.async.wait_group 1;" ::: "memory");
        __syncthreads();

        // issue chunk c+2 into slot (c+2)%3 (data of chunk c-1, reads done)
        const int nc = c + NSTAGE - 1;
        if (nc < 16) {
            const uint32_t so = (nc % NSTAGE) * STG_PAIR;
            const int kf = nc * 32;
            cpa16(so + xdst0, xsrc0 + kf);
            cpa16(so + xdst1, xsrc1 + kf);
            cpa16(so + wdst0, wsrc0 + kf);
            cpa16(so + wdst1, wsrc1 + kf);
        }
        asm volatile("cp.async.commit_group;" ::: "memory");

        const uint32_t slot = (c % NSTAGE) * STG_PAIR;
        const uint32_t aa = sb + slot + a_base;
        const uint32_t bb = sb + slot + b_base;

#pragma unroll
        for (int kstep = 0; kstep < 2; kstep++) {
            const uint32_t kb = kstep * 64;
            float4 A0, A1;
            asm volatile("ld.shared.v4.f32 {%0,%1,%2,%3}, [%4];"
                : "=f"(A0.x), "=f"(A0.y), "=f"(A0.z), "=f"(A0.w) : "r"(aa + kb));
            asm volatile("ld.shared.v4.f32 {%0,%1,%2,%3}, [%4];"
                : "=f"(A1.x), "=f"(A1.y), "=f"(A1.z), "=f"(A1.w) : "r"(aa + kb + 8 * 192));
            uint32_t ah[4], al[4];
            cvt_split(A0.x, A0.y, ah[0], al[0]);   // a0
            cvt_split(A1.x, A1.y, ah[1], al[1]);   // a1
            cvt_split(A0.z, A0.w, ah[2], al[2]);   // a2
            cvt_split(A1.z, A1.w, ah[3], al[3]);   // a3

#pragma unroll
            for (int t = 0; t < 4; t++) {
                float4 B;
                asm volatile("ld.shared.v4.f32 {%0,%1,%2,%3}, [%4];"
                    : "=f"(B.x), "=f"(B.y), "=f"(B.z), "=f"(B.w)
                    : "r"(bb + kb + t * 8 * 192));
                uint32_t bh0, bh1, bl0, bl1;
                cvt_split(B.x, B.y, bh0, bl0);
                cvt_split(B.z, B.w, bh1, bl1);
                mma16816(acc[t], ah, bh0, bh1);    // hh
                mma16816(acc[t], ah, bl0, bl1);    // hl
                mma16816(acc[t], al, bh0, bh1);    // lh
            }
        }
    }

    const int orow = wm * 16 + (lane >> 2);
    const int ocol = n0 + wn * 32 + (lane & 3) * 2;
#pragma unroll
    for (int t = 0; t < 4; t++) {
        const int col = ocol + t * 8;
        *(float2*)&outp[orow * FDIM + col]       = make_float2(acc[t][0], acc[t][1]);
        *(float2*)&outp[(orow + 8) * FDIM + col] = make_float2(acc[t][2], acc[t][3]);
    }
}

// ============================================================
// Phase 2a: per-batch bin tables (unchanged from R8).
// ============================================================
__global__ __launch_bounds__(256) void binprep(const int* __restrict__ mask)
{
    __shared__ float  skk[FDIM];
    __shared__ float  svv[FDIM];
    __shared__ unsigned char sact[FDIM];
    __shared__ __align__(16) float4 sA[NBINS];
    __shared__ __align__(16) float4 sB[NBINS];
    __shared__ float red[16];
    __shared__ int   wsum[8];
    __shared__ int   wbase[8];

    const int b    = blockIdx.x;
    const int tid  = threadIdx.x;
    const int lane = tid & 31;
    const int wid  = tid >> 5;
    const int off  = b * FDIM;
    const int* __restrict__ mrow = mask + off;

    float lmax = 0.0f, lmin = 0.0f;   // include 0
#pragma unroll
    for (int s = 0; s < 8; s++) {
        const int j = tid + s * 256;
        const int m = mrow[j];
        float kv = 0.0f, vv = 0.0f;
#pragma unroll
        for (int sp = 0; sp < NSPLIT; sp++) {
            kv += g_part[sp][1][off + j];
            vv += g_part[sp][2][off + j];
        }
        skk[j] = kv; svv[j] = vv; sact[j] = (unsigned char)m;
        if (m) { lmax = fmaxf(lmax, kv); lmin = fminf(lmin, kv); }
    }
#pragma unroll
    for (int o = 16; o; o >>= 1) {
        lmax = fmaxf(lmax, __shfl_xor_sync(0xffffffffu, lmax, o));
        lmin = fminf(lmin, __shfl_xor_sync(0xffffffffu, lmin, o));
    }
    if (lane == 0) { red[wid] = lmax; red[8 + wid] = lmin; }
    if (tid < NBINS) {
        sA[tid] = make_float4(0.f, 0.f, 0.f, 0.f);
        sB[tid] = make_float4(0.f, 0.f, 0.f, 0.f);
    }
    __syncthreads();

    float kmax = red[0], kmin = red[8];
#pragma unroll
    for (int w = 1; w < 8; w++) {
        kmax = fmaxf(kmax, red[w]);
        kmin = fminf(kmin, red[8 + w]);
    }
    const float range = fmaxf(kmax - kmin, 1e-12f);
    const float dlt   = range / NBINS;
    const float invd  = NBINS / range;

#pragma unroll
    for (int s = 0; s < 8; s++) {
        const int j = tid + s * 256;
        if (sact[j]) {
            const float k = skk[j];
            const float v = svv[j];
            int bi = (int)((k - kmin) * invd);
            bi = bi < 0 ? 0 : (bi > NBINS - 1 ? NBINS - 1 : bi);
            const float d  = k - (kmin + (bi + 0.5f) * dlt);
            const float d1 = C1T * d;
            const float d2 = C2T * d * d;
            const float d3 = C3T * d * d * d;
            atomicAdd(&sA[bi].x, 1.0f);
            atomicAdd(&sA[bi].y, v);
            atomicAdd(&sA[bi].z, d1);
            atomicAdd(&sA[bi].w, d1 * v);
            atomicAdd(&sB[bi].x, d2);
            atomicAdd(&sB[bi].y, d2 * v);
            atomicAdd(&sB[bi].z, d3);
            atomicAdd(&sB[bi].w, d3 * v);
        }
    }
    __syncthreads();

    const int flag = (tid < NBINS) && (sA[tid].x > 0.0f);
    int inc = flag;
#pragma unroll
    for (int o = 1; o < 32; o <<= 1) {
        int t = __shfl_up_sync(0xffffffffu, inc, o);
        if (lane >= o) inc += t;
    }
    if (lane == 31) wsum[wid] = inc;
    __syncthreads();
    if (tid < 8) {
        int v = wsum[tid];
#pragma unroll
        for (int o = 1; o < 8; o <<= 1) {
            int t = __shfl_up_sync(0xffu, v, o);
            if (tid >= o) v += t;
        }
        wbase[tid] = v;
    }
    __syncthreads();
    const int total = wbase[7];
    const int nbPad = (total + 3) & ~3;
    if (flag) {
        const int slot = (wid ? wbase[wid - 1] : 0) + inc - 1;
        g_binK[b][slot] = kmin + (tid + 0.5f) * dlt;
        g_binA[b][slot] = sA[tid];
        g_binB[b][slot] = sB[tid];
    }
    if (tid >= total && tid < nbPad) {
        g_binK[b][tid] = 0.0f;
        g_binA[b][tid] = make_float4(0.f, 0.f, 0.f, 0.f);
        g_binB[b][tid] = make_float4(0.f, 0.f, 0.f, 0.f);
    }
    if (tid == 0) {
        g_nb[b] = nbPad;
        g_kext[b] = make_float2(kmax, kmin);
    }
}

// ============================================================
// Phase 2b: attended[b,i] via bin tables (unchanged from R8).
// ============================================================
__global__ __launch_bounds__(256) void attn2(float* __restrict__ out)
{
    __shared__ float sK[NBINS];
    __shared__ __align__(16) float4 sAA[NBINS];
    __shared__ __align__(16) float4 sBB[NBINS];

    const int b   = blockIdx.y;
    const int tid = threadIdx.x;
    const int off = b * FDIM;

    const int    nb = g_nb[b];
    const float2 ke = g_kext[b];

    for (int t = tid; t < nb; t += 256) {
        sK[t]  = g_binK[b][t];
        sAA[t] = g_binA[b][t];
        sBB[t] = g_binB[b][t];
    }
    __syncthreads();

    const int i = blockIdx.x * 256 + tid;
    float qraw = 0.0f;
#pragma unroll
    for (int sp = 0; sp < NSPLIT; sp++) qraw += g_part[sp][0][off + i];
    const float qs   = qraw * LOG2E;
    const float m2   = (qs >= 0.0f) ? qs * ke.x : qs * ke.y;
    const float negm = -m2;
    unsigned long long qs2;
    asm("mov.b64 %0, {%1, %1};" : "=l"(qs2) : "r"(__float_as_uint(qs)));

    unsigned long long acc = 0ull;

#pragma unroll 2
    for (int p = 0; p < nb; p++) {
        const float kc = sK[p];
        ulonglong2 A = *(const ulonglong2*)&sAA[p];
        ulonglong2 B = *(const ulonglong2*)&sBB[p];
        float t = fmaf(qs, kc, negm);
        float e;
        asm("ex2.approx.ftz.f32 %0, %1;" : "=f"(e) : "f"(t));
        unsigned long long e2, H;
        asm("mov.b64 %0, {%1, %1};" : "=l"(e2) : "r"(__float_as_uint(e)));
        asm("fma.rn.f32x2 %0, %1, %2, %3;" : "=l"(H) : "l"(qs2), "l"(B.y), "l"(B.x));
        asm("fma.rn.f32x2 %0, %1, %2, %3;" : "=l"(H) : "l"(qs2), "l"(H), "l"(A.y));
        asm("fma.rn.f32x2 %0, %1, %2, %3;" : "=l"(H) : "l"(qs2), "l"(H), "l"(A.x));
        asm("fma.rn.f32x2 %0, %1, %2, %0;" : "+l"(acc) : "l"(e2), "l"(H));
    }

    unsigned int dlo, dhi;
    asm("mov.b64 {%0, %1}, %2;" : "=r"(dlo), "=r"(dhi) : "l"(acc));
    out[off + i] = __uint_as_float(dhi) / __uint_as_float(dlo);
}

extern "C" void kernel_launch(void* const* d_in, const int* in_sizes, int n_in,
                              void* d_out, int out_size)
{
    const float* x    = (const float*)d_in[0];
    const int*   mask = (const int*)d_in[1];
    const float* Wq   = (const float*)d_in[2];
    const float* Wk   = (const float*)d_in[3];
    const float* Wv   = (const float*)d_in[4];
    float* out = (float*)d_out;

    cudaFuncSetAttribute(gemm_mma, cudaFuncAttributeMaxDynamicSharedMemorySize, GEMM_SMEM);
    gemm_mma<<<384, 256, GEMM_SMEM>>>(x, Wq, Wk, Wv);
    binprep<<<BATCH, 256>>>(mask);
    attn2<<<dim3(FDIM / 256, BATCH), 256>>>(out);
}

// round 10
// speedup vs baseline: 3.7112x; 1.0956x over previous
#include <cuda_runtime.h>
#include <cstdint>

#define FDIM 2048
#define BATCH 64
#define LOG2E 1.4426950408889634f
#define NSPLIT 4
#define NBINS 128
#define C1T 0.69314718056f     // ln2
#define C2T 0.24022650696f     // ln2^2/2
#define C3T 0.05550410866f     // ln2^3/6

// K-split partial results: g_part[ksplit][0=q,1=k,2=v][b*F]
__device__ float g_part[NSPLIT][3][BATCH * FDIM];

// bin tables
__device__ float  g_binK[BATCH][NBINS];
__device__ float4 g_binA[BATCH][NBINS];   // {S0d,S0n,S1d,S1n}
__device__ float4 g_binB[BATCH][NBINS];   // {S2d,S2n,S3d,S3n}
__device__ int    g_nb[BATCH];
__device__ float2 g_kext[BATCH];          // {kmax', kmin'} (0 included)

// split a,b into bf16 hi pair + bf16 lo (residual) pair; a = low half
__device__ __forceinline__ void cvt_split(float a, float b, uint32_t& hi, uint32_t& lo) {
    uint32_t h;
    asm("cvt.rn.bf16x2.f32 %0, %1, %2;" : "=r"(h) : "f"(b), "f"(a));
    float ra = __uint_as_float(h << 16);
    float rb = __uint_as_float(h & 0xffff0000u);
    asm("cvt.rn.bf16x2.f32 %0, %1, %2;" : "=r"(lo) : "f"(b - rb), "f"(a - ra));
    hi = h;
}

__device__ __forceinline__ void mma16816(float* c, const uint32_t* a, uint32_t b0, uint32_t b1) {
    asm volatile("mma.sync.aligned.m16n8k16.row.col.f32.bf16.bf16.f32 "
        "{%0,%1,%2,%3}, {%4,%5,%6,%7}, {%8,%9}, {%0,%1,%2,%3};"
        : "+f"(c[0]), "+f"(c[1]), "+f"(c[2]), "+f"(c[3])
        : "r"(a[0]), "r"(a[1]), "r"(a[2]), "r"(a[3]), "r"(b0), "r"(b1));
}

__device__ __forceinline__ void cpa16(uint32_t dst, const void* src) {
    asm volatile("cp.async.cg.shared.global [%0], [%1], 16;" :: "r"(dst), "l"(src));
}

// ============================================================
// Phase 1: warp-MMA GEMM, bf16 error-split (hh + hl + lh),
// 3-stage cp.async pipeline of raw fp32 tiles; fragments via
// direct LDS.128 + in-register convert. 3 CTAs/SM -> all 384
// blocks resident (single wave, no tail).
// ============================================================
#define SPITCH 48                      // fp32 per smem row (192B = 64 mod 128)
#define STG_ARR (64 * SPITCH * 4)      // 12288 B per array per stage
#define STG_PAIR (2 * STG_ARR)         // 24576 B per stage
#define NSTAGE 3
#define GEMM_SMEM (NSTAGE * STG_PAIR)  // 73728 B

__global__ __launch_bounds__(256, 3) void gemm_mma(
    const float* __restrict__ x,
    const float* __restrict__ Wq,
    const float* __restrict__ Wk,
    const float* __restrict__ Wv)
{
    extern __shared__ char smem[];
    const uint32_t sb = (uint32_t)__cvta_generic_to_shared(smem);

    const int tid  = threadIdx.x;
    const int wid  = tid >> 5;
    const int lane = tid & 31;

    const int bx   = blockIdx.x;
    const int ks   = bx & 3;
    const int nt   = (bx >> 2) & 31;
    const int wsel = bx >> 7;
    const float* __restrict__ W = (wsel == 0) ? Wq : ((wsel == 1) ? Wk : Wv);
    float* __restrict__ outp = g_part[ks][wsel];
    const int k0 = ks * 512;
    const int n0 = nt * 64;

    const int wm = wid >> 1;           // m quarter
    const int wn = wid & 1;            // n half
    const int gid  = lane >> 2;
    const int tidq = lane & 3;

    // cp.async loader mapping: 2 rows per thread per array
    const int lrow = tid >> 3;         // 0..31 (+32 for second)
    const int lc16 = tid & 7;          // 16B col within 128B row-chunk
    const float* xsrc0 = x + lrow * FDIM + k0 + lc16 * 4;
    const float* xsrc1 = xsrc0 + 32 * FDIM;
    const float* wsrc0 = W + (n0 + lrow) * FDIM + k0 + lc16 * 4;
    const float* wsrc1 = wsrc0 + 32 * FDIM;
    const uint32_t xdst0 = sb + lrow * 192 + lc16 * 16;
    const uint32_t xdst1 = xdst0 + 32 * 192;
    const uint32_t wdst0 = xdst0 + STG_ARR;
    const uint32_t wdst1 = wdst0 + 32 * 192;

    float acc[4][4];
#pragma unroll
    for (int i = 0; i < 4; i++)
#pragma unroll
        for (int j = 0; j < 4; j++) acc[i][j] = 0.0f;

    // fragment LDS addresses (within a stage)
    const uint32_t a_base = (uint32_t)((wm * 16 + gid) * 192 + tidq * 16);
    const uint32_t b_base = (uint32_t)(STG_ARR + (wn * 32 + gid) * 192 + tidq * 16);

    // prologue: stages 0,1 = chunks 0,1
#pragma unroll
    for (int pc = 0; pc < NSTAGE - 1; pc++) {
        const uint32_t so = pc * STG_PAIR;
        const int kf = pc * 32;
        cpa16(so + xdst0, xsrc0 + kf);
        cpa16(so + xdst1, xsrc1 + kf);
        cpa16(so + wdst0, wsrc0 + kf);
        cpa16(so + wdst1, wsrc1 + kf);
        asm volatile("cp.async.commit_group;" ::: "memory");
    }

    for (int c = 0; c < 16; c++) {
        asm volatile("cp.async.wait_group 1;" ::: "memory");
        __syncthreads();

        // issue chunk c+2 into slot (c+2)%3 (data of chunk c-1, reads done)
        const int nc = c + NSTAGE - 1;
        if (nc < 16) {
            const uint32_t so = (nc % NSTAGE) * STG_PAIR;
            const int kf = nc * 32;
            cpa16(so + xdst0, xsrc0 + kf);
            cpa16(so + xdst1, xsrc1 + kf);
            cpa16(so + wdst0, wsrc0 + kf);
            cpa16(so + wdst1, wsrc1 + kf);
        }
        asm volatile("cp.async.commit_group;" ::: "memory");

        const uint32_t slot = (c % NSTAGE) * STG_PAIR;
        const uint32_t aa = sb + slot + a_base;
        const uint32_t bb = sb + slot + b_base;

#pragma unroll
        for (int kstep = 0; kstep < 2; kstep++) {
            const uint32_t kb = kstep * 64;
            float4 A0, A1;
            asm volatile("ld.shared.v4.f32 {%0,%1,%2,%3}, [%4];"
                : "=f"(A0.x), "=f"(A0.y), "=f"(A0.z), "=f"(A0.w) : "r"(aa + kb));
            asm volatile("ld.shared.v4.f32 {%0,%1,%2,%3}, [%4];"
                : "=f"(A1.x), "=f"(A1.y), "=f"(A1.z), "=f"(A1.w) : "r"(aa + kb + 8 * 192));
            uint32_t ah[4], al[4];
            cvt_split(A0.x, A0.y, ah[0], al[0]);
            cvt_split(A1.x, A1.y, ah[1], al[1]);
            cvt_split(A0.z, A0.w, ah[2], al[2]);
            cvt_split(A1.z, A1.w, ah[3], al[3]);

#pragma unroll
            for (int t = 0; t < 4; t++) {
                float4 B;
                asm volatile("ld.shared.v4.f32 {%0,%1,%2,%3}, [%4];"
                    : "=f"(B.x), "=f"(B.y), "=f"(B.z), "=f"(B.w)
                    : "r"(bb + kb + t * 8 * 192));
                uint32_t bh0, bh1, bl0, bl1;
                cvt_split(B.x, B.y, bh0, bl0);
                cvt_split(B.z, B.w, bh1, bl1);
                mma16816(acc[t], ah, bh0, bh1);    // hh
                mma16816(acc[t], ah, bl0, bl1);    // hl
                mma16816(acc[t], al, bh0, bh1);    // lh
            }
        }
    }

    const int orow = wm * 16 + (lane >> 2);
    const int ocol = n0 + wn * 32 + (lane & 3) * 2;
#pragma unroll
    for (int t = 0; t < 4; t++) {
        const int col = ocol + t * 8;
        *(float2*)&outp[orow * FDIM + col]       = make_float2(acc[t][0], acc[t][1]);
        *(float2*)&outp[(orow + 8) * FDIM + col] = make_float2(acc[t][2], acc[t][3]);
    }
}

// ============================================================
// Phase 2a: per-batch bin tables. 512 threads/block now.
// ============================================================
__global__ __launch_bounds__(512) void binprep(const int* __restrict__ mask)
{
    __shared__ float  skk[FDIM];
    __shared__ float  svv[FDIM];
    __shared__ unsigned char sact[FDIM];
    __shared__ __align__(16) float4 sA[NBINS];
    __shared__ __align__(16) float4 sB[NBINS];
    __shared__ float red[32];
    __shared__ int   wsum[16];
    __shared__ int   wbase[16];

    const int b    = blockIdx.x;
    const int tid  = threadIdx.x;
    const int lane = tid & 31;
    const int wid  = tid >> 5;     // 0..15
    const int off  = b * FDIM;
    const int* __restrict__ mrow = mask + off;

    float lmax = 0.0f, lmin = 0.0f;   // include 0
#pragma unroll
    for (int s = 0; s < 4; s++) {
        const int j = tid + s * 512;
        const int m = mrow[j];
        float kv = 0.0f, vv = 0.0f;
#pragma unroll
        for (int sp = 0; sp < NSPLIT; sp++) {
            kv += g_part[sp][1][off + j];
            vv += g_part[sp][2][off + j];
        }
        skk[j] = kv; svv[j] = vv; sact[j] = (unsigned char)m;
        if (m) { lmax = fmaxf(lmax, kv); lmin = fminf(lmin, kv); }
    }
#pragma unroll
    for (int o = 16; o; o >>= 1) {
        lmax = fmaxf(lmax, __shfl_xor_sync(0xffffffffu, lmax, o));
        lmin = fminf(lmin, __shfl_xor_sync(0xffffffffu, lmin, o));
    }
    if (lane == 0) { red[wid] = lmax; red[16 + wid] = lmin; }
    if (tid < NBINS) {
        sA[tid] = make_float4(0.f, 0.f, 0.f, 0.f);
        sB[tid] = make_float4(0.f, 0.f, 0.f, 0.f);
    }
    __syncthreads();

    float kmax = red[0], kmin = red[16];
#pragma unroll
    for (int w = 1; w < 16; w++) {
        kmax = fmaxf(kmax, red[w]);
        kmin = fminf(kmin, red[16 + w]);
    }
    const float range = fmaxf(kmax - kmin, 1e-12f);
    const float dlt   = range / NBINS;
    const float invd  = NBINS / range;

#pragma unroll
    for (int s = 0; s < 4; s++) {
        const int j = tid + s * 512;
        if (sact[j]) {
            const float k = skk[j];
            const float v = svv[j];
            int bi = (int)((k - kmin) * invd);
            bi = bi < 0 ? 0 : (bi > NBINS - 1 ? NBINS - 1 : bi);
            const float d  = k - (kmin + (bi + 0.5f) * dlt);
            const float d1 = C1T * d;
            const float d2 = C2T * d * d;
            const float d3 = C3T * d * d * d;
            atomicAdd(&sA[bi].x, 1.0f);
            atomicAdd(&sA[bi].y, v);
            atomicAdd(&sA[bi].z, d1);
            atomicAdd(&sA[bi].w, d1 * v);
            atomicAdd(&sB[bi].x, d2);
            atomicAdd(&sB[bi].y, d2 * v);
            atomicAdd(&sB[bi].z, d3);
            atomicAdd(&sB[bi].w, d3 * v);
        }
    }
    __syncthreads();

    // compact non-empty bins (NBINS=128 flags live in warps 0..3)
    const int flag = (tid < NBINS) && (sA[tid].x > 0.0f);
    int inc = flag;
#pragma unroll
    for (int o = 1; o < 32; o <<= 1) {
        int t = __shfl_up_sync(0xffffffffu, inc, o);
        if (lane >= o) inc += t;
    }
    if (lane == 31) wsum[wid] = inc;
    __syncthreads();
    if (tid < 16) {
        int v = wsum[tid];
#pragma unroll
        for (int o = 1; o < 16; o <<= 1) {
            int t = __shfl_up_sync(0xffffu, v, o);
            if (tid >= o) v += t;
        }
        wbase[tid] = v;
    }
    __syncthreads();
    const int total = wbase[15];
    const int nbPad = (total + 3) & ~3;
    if (flag) {
        const int slot = (wid ? wbase[wid - 1] : 0) + inc - 1;
        g_binK[b][slot] = kmin + (tid + 0.5f) * dlt;
        g_binA[b][slot] = sA[tid];
        g_binB[b][slot] = sB[tid];
    }
    if (tid >= total && tid < nbPad) {
        g_binK[b][tid] = 0.0f;
        g_binA[b][tid] = make_float4(0.f, 0.f, 0.f, 0.f);
        g_binB[b][tid] = make_float4(0.f, 0.f, 0.f, 0.f);
    }
    if (tid == 0) {
        g_nb[b] = nbPad;
        g_kext[b] = make_float2(kmax, kmin);
    }
}

// ============================================================
// Phase 2b: attended[b,i] via bin tables.
// ============================================================
__global__ __launch_bounds__(256) void attn2(float* __restrict__ out)
{
    __shared__ float sK[NBINS];
    __shared__ __align__(16) float4 sAA[NBINS];
    __shared__ __align__(16) float4 sBB[NBINS];

    const int b   = blockIdx.y;
    const int tid = threadIdx.x;
    const int off = b * FDIM;

    const int    nb = g_nb[b];
    const float2 ke = g_kext[b];

    for (int t = tid; t < nb; t += 256) {
        sK[t]  = g_binK[b][t];
        sAA[t] = g_binA[b][t];
        sBB[t] = g_binB[b][t];
    }
    __syncthreads();

    const int i = blockIdx.x * 256 + tid;
    float qraw = 0.0f;
#pragma unroll
    for (int sp = 0; sp < NSPLIT; sp++) qraw += g_part[sp][0][off + i];
    const float qs   = qraw * LOG2E;
    const float m2   = (qs >= 0.0f) ? qs * ke.x : qs * ke.y;
    const float negm = -m2;
    unsigned long long qs2;
    asm("mov.b64 %0, {%1, %1};" : "=l"(qs2) : "r"(__float_as_uint(qs)));

    unsigned long long acc = 0ull;

#pragma unroll 2
    for (int p = 0; p < nb; p++) {
        const float kc = sK[p];
        ulonglong2 A = *(const ulonglong2*)&sAA[p];
        ulonglong2 B = *(const ulonglong2*)&sBB[p];
        float t = fmaf(qs, kc, negm);
        float e;
        asm("ex2.approx.ftz.f32 %0, %1;" : "=f"(e) : "f"(t));
        unsigned long long e2, H;
        asm("mov.b64 %0, {%1, %1};" : "=l"(e2) : "r"(__float_as_uint(e)));
        asm("fma.rn.f32x2 %0, %1, %2, %3;" : "=l"(H) : "l"(qs2), "l"(B.y), "l"(B.x));
        asm("fma.rn.f32x2 %0, %1, %2, %3;" : "=l"(H) : "l"(qs2), "l"(H), "l"(A.y));
        asm("fma.rn.f32x2 %0, %1, %2, %3;" : "=l"(H) : "l"(qs2), "l"(H), "l"(A.x));
        asm("fma.rn.f32x2 %0, %1, %2, %0;" : "+l"(acc) : "l"(e2), "l"(H));
    }

    unsigned int dlo, dhi;
    asm("mov.b64 {%0, %1}, %2;" : "=r"(dlo), "=r"(dhi) : "l"(acc));
    out[off + i] = __uint_as_float(dhi) / __uint_as_float(dlo);
}

extern "C" void kernel_launch(void* const* d_in, const int* in_sizes, int n_in,
                              void* d_out, int out_size)
{
    const float* x    = (const float*)d_in[0];
    const int*   mask = (const int*)d_in[1];
    const float* Wq   = (const float*)d_in[2];
    const float* Wk   = (const float*)d_in[3];
    const float* Wv   = (const float*)d_in[4];
    float* out = (float*)d_out;

    cudaFuncSetAttribute(gemm_mma, cudaFuncAttributeMaxDynamicSharedMemorySize, GEMM_SMEM);
    gemm_mma<<<384, 256, GEMM_SMEM>>>(x, Wq, Wk, Wv);
    binprep<<<BATCH, 512>>>(mask);
    attn2<<<dim3(FDIM / 256, BATCH), 256>>>(out);
}